// round 10
// baseline (speedup 1.0000x reference)
#include <cuda_runtime.h>

// d_w(theta) = A_w cos(theta) + B_w sin(theta),  A_w = cos(alpha_w)cos(beta_w),
// B_w = -sin(beta_w)  (the Rz param is dead for Z expvals).
// Phase-folded: d_w = R_w cos(theta - phi_w). With W'_k = W_k * prod_{j<=k} R_j:
//   out = c0*(W0' + c1*(W1' + c2*(W2' + c3*W3'))),  c_w = __cosf(theta_w - phi_w).
// => 1 MUFU per pixel. Fold on threads 0-3 per block, hidden under load latency.
// Grid is EXACTLY one wave (148 SM x 8 blocks); threads grid-stride over quads.

#define NQUADS   401408   // 8192 * 7 * 7 four-patch work units
#define NTHREADS 303104   // 1184 * 256

__device__ __forceinline__ float patch_ev(float t0, float t1, float t2, float t3,
                                          float4 P, float4 Wf) {
    float c0 = __cosf(t0 - P.x);
    float c1 = __cosf(t1 - P.y);
    float c2 = __cosf(t2 - P.z);
    float c3 = __cosf(t3 - P.w);
    return c0 * fmaf(c1, fmaf(c2, fmaf(c3, Wf.w, Wf.z), Wf.y), Wf.x);
}

// One quad = 4 patches: column-pair jj at patch-rows {i, i+7} of image b.
__device__ __forceinline__ void do_quad(int q, const float4* __restrict__ xr,
                                        float2* __restrict__ o2,
                                        float4 Pv, float4 Wf) {
    int jj = q % 7;           // pair-of-patches column (j = 2jj, 2jj+1)
    int r  = q / 7;
    int i  = r % 7;           // patch row in [0,7); also handles i+7
    int b  = r / 7;           // image

    int o0 = b * 196 + i * 14 + jj;
    float4 r0 = xr[o0];         // row 2i
    float4 r1 = xr[o0 + 7];     // row 2i+1
    float4 r2 = xr[o0 + 98];    // row 2(i+7)
    float4 r3 = xr[o0 + 105];   // row 2(i+7)+1

    float2 oA, oB;
    oA.x = patch_ev(r0.x, r0.y, r1.x, r1.y, Pv, Wf);
    oA.y = patch_ev(r0.z, r0.w, r1.z, r1.w, Pv, Wf);
    oB.x = patch_ev(r2.x, r2.y, r3.x, r3.y, Pv, Wf);
    oB.y = patch_ev(r2.z, r2.w, r3.z, r3.w, Pv, Wf);

    int q0 = b * 98 + i * 7 + jj;
    o2[q0]      = oA;
    o2[q0 + 49] = oB;
}

__global__ void __launch_bounds__(256, 8)
quanv_kernel(const float* __restrict__ x, const float* __restrict__ params,
             const float* __restrict__ W, float* __restrict__ out) {
    __shared__ float sphi[4], sR[4], sW[4];

    int t = blockIdx.x * 256 + threadIdx.x;

    // Front-batch the first quad's loads so they are in flight during the fold.
    const float4* xr = reinterpret_cast<const float4*>(x);
    int jj = t % 7;
    int r  = t / 7;
    int i  = r % 7;
    int b  = r / 7;
    int o0 = b * 196 + i * 14 + jj;
    float4 r0 = xr[o0];
    float4 r1 = xr[o0 + 7];
    float4 r2 = xr[o0 + 98];
    float4 r3 = xr[o0 + 105];

    // Per-block fold on threads 0-3 (fast intrinsics; atan2f on 4 threads only,
    // hidden under the x-load latency above).
    if (threadIdx.x < 4) {
        int w = threadIdx.x;
        float a  = params[3 * w + 0];
        float bb = params[3 * w + 1];
        float A = __cosf(a) * __cosf(bb);
        float B = -__sinf(bb);
        sR[w]   = sqrtf(fmaf(A, A, B * B));
        sphi[w] = atan2f(B, A);
        sW[w]   = W[w];
    }
    __syncthreads();

    float R0 = sR[0], R1 = sR[1], R2s = sR[2], R3s = sR[3];
    float p01 = R0 * R1, p012 = p01 * R2s;
    float4 Wf = make_float4(sW[0] * R0, sW[1] * p01, sW[2] * p012, sW[3] * p012 * R3s);
    float4 Pv = make_float4(sphi[0], sphi[1], sphi[2], sphi[3]);

    // Quad 1 (loads already in registers).
    float2* o2 = reinterpret_cast<float2*>(out);
    {
        float2 oA, oB;
        oA.x = patch_ev(r0.x, r0.y, r1.x, r1.y, Pv, Wf);
        oA.y = patch_ev(r0.z, r0.w, r1.z, r1.w, Pv, Wf);
        oB.x = patch_ev(r2.x, r2.y, r3.x, r3.y, Pv, Wf);
        oB.y = patch_ev(r2.z, r2.w, r3.z, r3.w, Pv, Wf);
        int q0 = b * 98 + i * 7 + jj;
        o2[q0]      = oA;
        o2[q0 + 49] = oB;
    }

    // Quad 2 (grid-stride): only the first 98304 threads (blocks 0-383).
    int t2 = t + NTHREADS;
    if (t2 < NQUADS)
        do_quad(t2, xr, o2, Pv, Wf);
}

extern "C" void kernel_launch(void* const* d_in, const int* in_sizes, int n_in,
                              void* d_out, int out_size) {
    const float* x      = (const float*)d_in[0];
    const float* params = (const float*)d_in[1];
    const float* W      = (const float*)d_in[2];
    float* out          = (float*)d_out;

    quanv_kernel<<<1184, 256>>>(x, params, W, out);
}

// round 11
// speedup vs baseline: 1.0180x; 1.0180x over previous
#include <cuda_runtime.h>

// d_w(theta) = A_w cos(theta) + B_w sin(theta),
//   A_w = cos(alpha_w)cos(beta_w), B_w = -sin(beta_w)  (Rz param is dead).
// Entangler: Z_k = prod_{j<=k} d_j  ->  out = d0*(W0 + d1*(W1 + d2*(W2 + d3*W3))).
// Fold = 12 fast MUFU on threads 0-3 (no libm slow path), fully hidden under
// the block's front-batched x loads. Main loop: __sincosf (2 MUFU/pixel).

__device__ __forceinline__ float patch_ev(float t0, float t1, float t2, float t3,
                                          float4 A, float4 B, float4 Wv) {
    float s, c;
    __sincosf(t0, &s, &c); float d0 = fmaf(A.x, c, B.x * s);
    __sincosf(t1, &s, &c); float d1 = fmaf(A.y, c, B.y * s);
    __sincosf(t2, &s, &c); float d2 = fmaf(A.z, c, B.z * s);
    __sincosf(t3, &s, &c); float d3 = fmaf(A.w, c, B.w * s);
    return d0 * fmaf(d1, fmaf(d2, fmaf(d3, Wv.w, Wv.z), Wv.y), Wv.x);
}

// One thread computes 2 horizontally-adjacent 2x2 patches.
// Threads: 8192 * 14 * 7 = 802816 = 3136 * 256 (exact, no bounds check).
__global__ void __launch_bounds__(256, 8)
quanv_kernel(const float* __restrict__ x, const float* __restrict__ params,
             const float* __restrict__ W, float* __restrict__ out) {
    __shared__ __align__(16) float sqc[12];   // A0..3, B0..3, W0..3

    int t  = blockIdx.x * 256 + threadIdx.x;
    int jj = t % 7;          // pair-of-patches column (j = 2jj, 2jj+1)
    int bi = t / 7;          // b*14 + i
    int i  = bi % 14;        // patch row
    int b  = bi / 14;        // image

    // Front-batch the streaming loads: in flight during the (tiny) fold below.
    const float4* xr = reinterpret_cast<const float4*>(x);
    int o0 = b * 196 + i * 14 + jj;
    float4 r0 = xr[o0];       // row 2i
    float4 r1 = xr[o0 + 7];   // row 2i+1

    // Trivial fold: fast intrinsics only (~50 cyc), no libm slow path, so the
    // barrier releases as soon as the param L1 loads land.
    if (threadIdx.x < 4) {
        int w = threadIdx.x;
        float a  = params[3 * w + 0];
        float bb = params[3 * w + 1];
        sqc[w]     = __cosf(a) * __cosf(bb);   // A_w
        sqc[4 + w] = -__sinf(bb);              // B_w
        sqc[8 + w] = W[w];
    }
    __syncthreads();

    const float4* qc = reinterpret_cast<const float4*>(sqc);
    float4 Av = qc[0], Bv = qc[1], Wv = qc[2];

    float2 o;
    o.x = patch_ev(r0.x, r0.y, r1.x, r1.y, Av, Bv, Wv);
    o.y = patch_ev(r0.z, r0.w, r1.z, r1.w, Av, Bv, Wv);

    // out (B,196): float2 index b*98 + i*7 + jj (8B aligned)
    reinterpret_cast<float2*>(out)[b * 98 + i * 7 + jj] = o;
}

extern "C" void kernel_launch(void* const* d_in, const int* in_sizes, int n_in,
                              void* d_out, int out_size) {
    const float* x      = (const float*)d_in[0];
    const float* params = (const float*)d_in[1];
    const float* W      = (const float*)d_in[2];
    float* out          = (float*)d_out;

    quanv_kernel<<<3136, 256>>>(x, params, W, out);
}

// round 12
// speedup vs baseline: 1.0481x; 1.0296x over previous
#include <cuda_runtime.h>

// d_w(theta) = A_w cos(theta) + B_w sin(theta),
//   A_w = cos(alpha_w)cos(beta_w), B_w = -sin(beta_w)  (Rz param is dead).
// Phase-folded: d_w = R_w cos(theta - phi_w),  R_w = |(A,B)|, phi_w = atan2(B,A).
// Entangler: Z_k = prod_{j<=k} d_j. With W'_k = W_k * prod_{j<=k} R_j:
//   out = c0*(W0' + c1*(W1' + c2*(W2' + c3*W3'))),  c_w = __cosf(theta_w - phi_w)
// => 1 MUFU + 1 FADD + ~1 FMA per pixel. The fold uses a branch-free
// polynomial atan2 + __fsqrt_rn (no libm slow path) on threads 0-3, fully
// hidden under the block's front-batched x loads.

__device__ __forceinline__ float fast_atan2f(float y, float x) {
    // Branch-free atan2, |err| ~ 1e-5 rad (far under the 1e-3 rel tolerance).
    float ax = fabsf(x), ay = fabsf(y);
    float mn = fminf(ax, ay), mx = fmaxf(ax, ay);
    float r  = __fdividef(mn, mx);           // in [0,1]
    float s  = r * r;
    // atan(r) minimax poly on [0,1]
    float p = fmaf(s, fmaf(s, fmaf(s, fmaf(s, 0.0208351f, -0.0851330f),
                                   0.1801410f), -0.3302995f), 0.9998660f) * r;
    p = (ay > ax) ? (1.5707963f - p) : p;    // reflect past 45 deg
    p = (x < 0.0f) ? (3.1415927f - p) : p;   // left half-plane
    return copysignf(p, y);
}

__device__ __forceinline__ float patch_ev(float t0, float t1, float t2, float t3,
                                          float4 P, float4 Wf) {
    float c0 = __cosf(t0 - P.x);
    float c1 = __cosf(t1 - P.y);
    float c2 = __cosf(t2 - P.z);
    float c3 = __cosf(t3 - P.w);
    return c0 * fmaf(c1, fmaf(c2, fmaf(c3, Wf.w, Wf.z), Wf.y), Wf.x);
}

// One thread computes 2 horizontally-adjacent 2x2 patches.
// Threads: 8192 * 14 * 7 = 802816 = 3136 * 256 (exact, no bounds check).
__global__ void __launch_bounds__(256, 8)
quanv_kernel(const float* __restrict__ x, const float* __restrict__ params,
             const float* __restrict__ W, float* __restrict__ out) {
    __shared__ __align__(16) float sqc[8];   // phi0..3, W'0..3

    int t  = blockIdx.x * 256 + threadIdx.x;
    int jj = t % 7;          // pair-of-patches column (j = 2jj, 2jj+1)
    int bi = t / 7;          // b*14 + i
    int i  = bi % 14;        // patch row
    int b  = bi / 14;        // image

    // Front-batch the streaming loads: in flight during the fold below.
    const float4* xr = reinterpret_cast<const float4*>(x);
    int o0 = b * 196 + i * 14 + jj;
    float4 r0 = xr[o0];       // row 2i
    float4 r1 = xr[o0 + 7];   // row 2i+1

    // Branch-free fold on threads 0-3 (~25 straight-line instrs, no libm):
    // releases the barrier as soon as the param loads land.
    if (threadIdx.x < 4) {
        int w = threadIdx.x;
        float a  = params[3 * w + 0];
        float bb = params[3 * w + 1];
        float A = __cosf(a) * __cosf(bb);
        float B = -__sinf(bb);
        sqc[w]     = fast_atan2f(B, A);              // phi_w
        sqc[4 + w] = __fsqrt_rn(fmaf(A, A, B * B));  // R_w (combined below)
    }
    __syncthreads();

    // Cumulative weights from smem broadcasts (per-thread, no 2nd barrier).
    float R0 = sqc[4], R1 = sqc[5], R2 = sqc[6], R3 = sqc[7];
    float p01 = R0 * R1, p012 = p01 * R2;
    float4 Wf = make_float4(W[0] * R0, W[1] * p01, W[2] * p012, W[3] * p012 * R3);
    float4 Pv = make_float4(sqc[0], sqc[1], sqc[2], sqc[3]);

    float2 o;
    o.x = patch_ev(r0.x, r0.y, r1.x, r1.y, Pv, Wf);
    o.y = patch_ev(r0.z, r0.w, r1.z, r1.w, Pv, Wf);

    // out (B,196): float2 index b*98 + i*7 + jj (8B aligned)
    reinterpret_cast<float2*>(out)[b * 98 + i * 7 + jj] = o;
}

extern "C" void kernel_launch(void* const* d_in, const int* in_sizes, int n_in,
                              void* d_out, int out_size) {
    const float* x      = (const float*)d_in[0];
    const float* params = (const float*)d_in[1];
    const float* W      = (const float*)d_in[2];
    float* out          = (float*)d_out;

    quanv_kernel<<<3136, 256>>>(x, params, W, out);
}